// round 4
// baseline (speedup 1.0000x reference)
#include <cuda_runtime.h>
#include <cstdint>

#define NN_MAX 50000
#define NE_MAX 800000
#define D 64

#define TE 64
#define XS_STRIDE 196   // 192 + 4 pad: bank = (4e + k) % 32
#define HS_STRIDE 68    // 64 + 4 pad
#define NXS_STRIDE 132  // 128 + 4 pad

// ---------------- device scratch (no runtime allocation allowed) ----------------
__device__ int   g_is64;
__device__ int   g_src[NE_MAX];
__device__ int   g_dst[NE_MAX];
__device__ float g_accum[(size_t)NN_MAX * D];

// ---------------- dtype detection for edge_index ----------------
// If the buffer is int64, every int64 word is a valid node id < NN_MAX.
// If it is int32, interpreting pairs as int64 gives huge values (hi word != 0
// with overwhelming probability). Check first 64 int64 words.
__global__ void detect_kernel(const void* ei) {
    const long long* p = (const long long*)ei;
    bool ok = true;
    for (int i = threadIdx.x; i < 64; i += 32) {
        long long v = p[i];
        if (v < 0 || v >= NN_MAX) ok = false;
    }
    unsigned m = __ballot_sync(0xffffffffu, ok);
    if (threadIdx.x == 0) g_is64 = (m == 0xffffffffu) ? 1 : 0;
}

__global__ void convert_kernel(const void* ei, int E) {
    int i = blockIdx.x * blockDim.x + threadIdx.x;
    if (i >= E) return;
    if (g_is64) {
        const long long* p = (const long long*)ei;
        g_src[i] = (int)p[i];
        g_dst[i] = (int)p[(size_t)E + i];
    } else {
        const int* p = (const int*)ei;
        g_src[i] = p[i];
        g_dst[i] = p[E + i];
    }
}

// accum = features  (re-done every replay; graph replays must be idempotent)
__global__ void init_accum_kernel(const float* __restrict__ feat, int n4) {
    int i = blockIdx.x * blockDim.x + threadIdx.x;
    if (i < n4) ((float4*)g_accum)[i] = ((const float4*)feat)[i];
}

// ---------------- edge MLP + scatter ----------------
// Per tile of 64 edges: X[64][192] = [feat[src] | ef | feat[dst]] in smem,
// h1 = relu(X @ W1^T + b1), h2 = h1 @ W2^T + b2, atomicAdd h2 into accum[src].
// Thread blocking: 4 edges x 4 outputs (16 accumulators).
__global__ __launch_bounds__(256, 1)
void edge_kernel(const float* __restrict__ feat,
                 const float* __restrict__ ef,
                 const float* __restrict__ W1, const float* __restrict__ b1,
                 const float* __restrict__ W2, const float* __restrict__ b2,
                 int E, int ntiles) {
    extern __shared__ float sm[];
    float* W1s = sm;                        // [192][64]  W1s[k*64+j] = W1[j][k]
    float* W2s = W1s + 192 * 64;            // [64][64]   W2s[j*64+i] = W2[i][j]
    float* Xs  = W2s + 64 * 64;             // [TE][XS_STRIDE]
    float* Hs  = Xs + TE * XS_STRIDE;       // [TE][HS_STRIDE]
    int*   srcs = (int*)(Hs + TE * HS_STRIDE);
    int*   dsts = srcs + TE;

    const int tid = threadIdx.x;

    // transpose-load weights into smem (once per block; L2 hits)
    for (int idx = tid; idx < 192 * 64; idx += 256) {
        int k = idx >> 6, j = idx & 63;
        W1s[idx] = W1[j * 192 + k];
    }
    for (int idx = tid; idx < 64 * 64; idx += 256) {
        int j = idx >> 6, i = idx & 63;
        W2s[idx] = W2[i * 64 + j];
    }

    const int jg = tid & 15;        // output group: j0 = jg*4
    const int ep = tid >> 4;        // edge group:   ebase = ep*4
    const int j0 = jg * 4;
    const int ebase = ep * 4;

    float bb1[4], bb2[4];
#pragma unroll
    for (int u = 0; u < 4; u++) { bb1[u] = b1[j0 + u]; bb2[u] = b2[j0 + u]; }

    for (int t = blockIdx.x; t < ntiles; t += gridDim.x) {
        const int base = t * TE;
        __syncthreads();  // protects smem reuse across iterations (and first-iter weight load)

        if (tid < TE) {
            int e = base + tid;
            srcs[tid] = (e < E) ? g_src[e] : 0;
            dsts[tid] = (e < E) ? g_dst[e] : 0;
        }
        __syncthreads();

        // gather X tile: 64 edges x 48 float4
        for (int idx = tid; idx < TE * 48; idx += 256) {
            int e = idx / 48, q = idx - e * 48;
            int ge = base + e;
            float4 v;
            if (q < 16)      v = ((const float4*)(feat + (size_t)srcs[e] * D))[q];
            else if (q < 32) v = (ge < E) ? ((const float4*)(ef + (size_t)ge * D))[q - 16]
                                          : make_float4(0.f, 0.f, 0.f, 0.f);
            else             v = ((const float4*)(feat + (size_t)dsts[e] * D))[q - 32];
            *(float4*)(Xs + e * XS_STRIDE + q * 4) = v;
        }
        __syncthreads();

        // ---- stage 1: 192 -> 64, relu ----
        float acc[4][4];
#pragma unroll
        for (int c = 0; c < 4; c++)
#pragma unroll
            for (int u = 0; u < 4; u++) acc[c][u] = 0.f;

        const float* xrow = Xs + ebase * XS_STRIDE;
#pragma unroll 8
        for (int k = 0; k < 192; k++) {
            float x0 = xrow[k];
            float x1 = xrow[XS_STRIDE + k];
            float x2 = xrow[2 * XS_STRIDE + k];
            float x3 = xrow[3 * XS_STRIDE + k];
            float4 w = *(const float4*)(W1s + (k << 6) + j0);
            acc[0][0] += x0 * w.x; acc[0][1] += x0 * w.y; acc[0][2] += x0 * w.z; acc[0][3] += x0 * w.w;
            acc[1][0] += x1 * w.x; acc[1][1] += x1 * w.y; acc[1][2] += x1 * w.z; acc[1][3] += x1 * w.w;
            acc[2][0] += x2 * w.x; acc[2][1] += x2 * w.y; acc[2][2] += x2 * w.z; acc[2][3] += x2 * w.w;
            acc[3][0] += x3 * w.x; acc[3][1] += x3 * w.y; acc[3][2] += x3 * w.z; acc[3][3] += x3 * w.w;
        }
#pragma unroll
        for (int c = 0; c < 4; c++) {
            float4 h;
            h.x = fmaxf(acc[c][0] + bb1[0], 0.f);
            h.y = fmaxf(acc[c][1] + bb1[1], 0.f);
            h.z = fmaxf(acc[c][2] + bb1[2], 0.f);
            h.w = fmaxf(acc[c][3] + bb1[3], 0.f);
            *(float4*)(Hs + (ebase + c) * HS_STRIDE + j0) = h;
        }
        __syncthreads();

        // ---- stage 2: 64 -> 64 ----
#pragma unroll
        for (int c = 0; c < 4; c++)
#pragma unroll
            for (int u = 0; u < 4; u++) acc[c][u] = 0.f;

        const float* hrow = Hs + ebase * HS_STRIDE;
#pragma unroll 8
        for (int k = 0; k < 64; k++) {
            float x0 = hrow[k];
            float x1 = hrow[HS_STRIDE + k];
            float x2 = hrow[2 * HS_STRIDE + k];
            float x3 = hrow[3 * HS_STRIDE + k];
            float4 w = *(const float4*)(W2s + (k << 6) + j0);
            acc[0][0] += x0 * w.x; acc[0][1] += x0 * w.y; acc[0][2] += x0 * w.z; acc[0][3] += x0 * w.w;
            acc[1][0] += x1 * w.x; acc[1][1] += x1 * w.y; acc[1][2] += x1 * w.z; acc[1][3] += x1 * w.w;
            acc[2][0] += x2 * w.x; acc[2][1] += x2 * w.y; acc[2][2] += x2 * w.z; acc[2][3] += x2 * w.w;
            acc[3][0] += x3 * w.x; acc[3][1] += x3 * w.y; acc[3][2] += x3 * w.z; acc[3][3] += x3 * w.w;
        }

        // scatter (sum by src)
#pragma unroll
        for (int c = 0; c < 4; c++) {
            int e = ebase + c;
            if (base + e < E) {
                float* dstp = g_accum + (size_t)srcs[e] * D + j0;
                atomicAdd(dstp + 0, acc[c][0] + bb2[0]);
                atomicAdd(dstp + 1, acc[c][1] + bb2[1]);
                atomicAdd(dstp + 2, acc[c][2] + bb2[2]);
                atomicAdd(dstp + 3, acc[c][3] + bb2[3]);
            }
        }
    }
}

// ---------------- node MLP ----------------
// z = relu([feat | accum] @ W3^T + b3) @ W4^T + b4
__global__ __launch_bounds__(256, 1)
void node_kernel(const float* __restrict__ feat,
                 const float* __restrict__ W3, const float* __restrict__ b3,
                 const float* __restrict__ W4, const float* __restrict__ b4,
                 float* __restrict__ out, int N) {
    extern __shared__ float sm[];
    float* W3s = sm;                        // [128][64]
    float* W4s = W3s + 128 * 64;            // [64][64]
    float* Xs  = W4s + 64 * 64;             // [64][NXS_STRIDE]
    float* Hs  = Xs + 64 * NXS_STRIDE;      // [64][HS_STRIDE]

    const int tid = threadIdx.x;

    for (int idx = tid; idx < 128 * 64; idx += 256) {
        int k = idx >> 6, j = idx & 63;
        W3s[idx] = W3[j * 128 + k];
    }
    for (int idx = tid; idx < 64 * 64; idx += 256) {
        int j = idx >> 6, i = idx & 63;
        W4s[idx] = W4[i * 64 + j];
    }

    const int jg = tid & 15;
    const int ep = tid >> 4;
    const int j0 = jg * 4;
    const int ebase = ep * 4;

    float bb3[4], bb4[4];
#pragma unroll
    for (int u = 0; u < 4; u++) { bb3[u] = b3[j0 + u]; bb4[u] = b4[j0 + u]; }

    const int base = blockIdx.x * 64;
    __syncthreads();

    // gather: 64 nodes x 32 float4 (16 feat + 16 accum)
    for (int idx = tid; idx < 64 * 32; idx += 256) {
        int e = idx >> 5, q = idx & 31;
        int node = base + e;
        if (node >= N) node = N - 1;
        float4 v;
        if (q < 16) v = ((const float4*)(feat + (size_t)node * D))[q];
        else        v = ((const float4*)(g_accum + (size_t)node * D))[q - 16];
        *(float4*)(Xs + e * NXS_STRIDE + q * 4) = v;
    }
    __syncthreads();

    float acc[4][4];
#pragma unroll
    for (int c = 0; c < 4; c++)
#pragma unroll
        for (int u = 0; u < 4; u++) acc[c][u] = 0.f;

    const float* xrow = Xs + ebase * NXS_STRIDE;
#pragma unroll 8
    for (int k = 0; k < 128; k++) {
        float x0 = xrow[k];
        float x1 = xrow[NXS_STRIDE + k];
        float x2 = xrow[2 * NXS_STRIDE + k];
        float x3 = xrow[3 * NXS_STRIDE + k];
        float4 w = *(const float4*)(W3s + (k << 6) + j0);
        acc[0][0] += x0 * w.x; acc[0][1] += x0 * w.y; acc[0][2] += x0 * w.z; acc[0][3] += x0 * w.w;
        acc[1][0] += x1 * w.x; acc[1][1] += x1 * w.y; acc[1][2] += x1 * w.z; acc[1][3] += x1 * w.w;
        acc[2][0] += x2 * w.x; acc[2][1] += x2 * w.y; acc[2][2] += x2 * w.z; acc[2][3] += x2 * w.w;
        acc[3][0] += x3 * w.x; acc[3][1] += x3 * w.y; acc[3][2] += x3 * w.z; acc[3][3] += x3 * w.w;
    }
#pragma unroll
    for (int c = 0; c < 4; c++) {
        float4 h;
        h.x = fmaxf(acc[c][0] + bb3[0], 0.f);
        h.y = fmaxf(acc[c][1] + bb3[1], 0.f);
        h.z = fmaxf(acc[c][2] + bb3[2], 0.f);
        h.w = fmaxf(acc[c][3] + bb3[3], 0.f);
        *(float4*)(Hs + (ebase + c) * HS_STRIDE + j0) = h;
    }
    __syncthreads();

#pragma unroll
    for (int c = 0; c < 4; c++)
#pragma unroll
        for (int u = 0; u < 4; u++) acc[c][u] = 0.f;

    const float* hrow = Hs + ebase * HS_STRIDE;
#pragma unroll 8
    for (int k = 0; k < 64; k++) {
        float x0 = hrow[k];
        float x1 = hrow[HS_STRIDE + k];
        float x2 = hrow[2 * HS_STRIDE + k];
        float x3 = hrow[3 * HS_STRIDE + k];
        float4 w = *(const float4*)(W4s + (k << 6) + j0);
        acc[0][0] += x0 * w.x; acc[0][1] += x0 * w.y; acc[0][2] += x0 * w.z; acc[0][3] += x0 * w.w;
        acc[1][0] += x1 * w.x; acc[1][1] += x1 * w.y; acc[1][2] += x1 * w.z; acc[1][3] += x1 * w.w;
        acc[2][0] += x2 * w.x; acc[2][1] += x2 * w.y; acc[2][2] += x2 * w.z; acc[2][3] += x2 * w.w;
        acc[3][0] += x3 * w.x; acc[3][1] += x3 * w.y; acc[3][2] += x3 * w.z; acc[3][3] += x3 * w.w;
    }

#pragma unroll
    for (int c = 0; c < 4; c++) {
        int node = base + ebase + c;
        if (node < N) {
            float4 z;
            z.x = acc[c][0] + bb4[0];
            z.y = acc[c][1] + bb4[1];
            z.z = acc[c][2] + bb4[2];
            z.w = acc[c][3] + bb4[3];
            *(float4*)(out + (size_t)node * D + j0) = z;
        }
    }
}

// ---------------- launch ----------------
static const int EDGE_SMEM = (192 * 64 + 64 * 64 + TE * XS_STRIDE + TE * HS_STRIDE) * 4 + 2 * TE * 4;
static const int NODE_SMEM = (128 * 64 + 64 * 64 + 64 * NXS_STRIDE + 64 * HS_STRIDE) * 4;

extern "C" void kernel_launch(void* const* d_in, const int* in_sizes, int n_in,
                              void* d_out, int out_size) {
    const float* feat = (const float*)d_in[0];
    const void*  ei   = d_in[1];
    const float* ef   = (const float*)d_in[2];
    const float* W1   = (const float*)d_in[3];
    const float* b1   = (const float*)d_in[4];
    const float* W2   = (const float*)d_in[5];
    const float* b2   = (const float*)d_in[6];
    const float* W3   = (const float*)d_in[7];
    const float* b3   = (const float*)d_in[8];
    const float* W4   = (const float*)d_in[9];
    const float* b4   = (const float*)d_in[10];
    float* out = (float*)d_out;

    int N = in_sizes[0] / D;
    int E = in_sizes[2] / D;
    if (N > NN_MAX) N = NN_MAX;
    if (E > NE_MAX) E = NE_MAX;

    cudaFuncSetAttribute(edge_kernel, cudaFuncAttributeMaxDynamicSharedMemorySize, EDGE_SMEM);
    cudaFuncSetAttribute(node_kernel, cudaFuncAttributeMaxDynamicSharedMemorySize, NODE_SMEM);

    detect_kernel<<<1, 32>>>(ei);
    convert_kernel<<<(E + 255) / 256, 256>>>(ei, E);
    init_accum_kernel<<<(N * 16 + 255) / 256, 256>>>(feat, N * 16);

    int etiles = (E + TE - 1) / TE;
    edge_kernel<<<148, 256, EDGE_SMEM>>>(feat, ef, W1, b1, W2, b2, E, etiles);

    int ntiles = (N + 63) / 64;
    node_kernel<<<ntiles, 256, NODE_SMEM>>>(feat, W3, b3, W4, b4, out, N);
}

// round 7
// speedup vs baseline: 1.1192x; 1.1192x over previous
#include <cuda_runtime.h>
#include <cstdint>

#define NN_MAX 50000
#define NE_MAX 800000
#define D 64

#define TE 128          // edges per tile (edge kernel)
#define XS_STRIDE 196   // 192 + 4 pad
#define HS_STRIDE 68    // 64 + 4 pad
#define NXS_STRIDE 132  // 128 + 4 pad

// ---------------- device scratch (no runtime allocation allowed) ----------------
__device__ int   g_is64;
__device__ int   g_src[NE_MAX];
__device__ int   g_dst[NE_MAX];
__device__ float g_accum[(size_t)NN_MAX * D];

// ---------------- f32x2 helpers (Blackwell packed fp32 FMA) ----------------
__device__ __forceinline__ unsigned long long packf2(float x) {
    unsigned long long r;
    asm("mov.b64 %0, {%1, %1};" : "=l"(r) : "f"(x));
    return r;
}
__device__ __forceinline__ void ffma2(unsigned long long& d,
                                      unsigned long long a,
                                      unsigned long long b) {
    asm("fma.rn.f32x2 %0, %1, %2, %3;" : "=l"(d) : "l"(a), "l"(b), "l"(d));
}
__device__ __forceinline__ float2 unpackf2(unsigned long long v) {
    float lo, hi;
    asm("mov.b64 {%0, %1}, %2;" : "=f"(lo), "=f"(hi) : "l"(v));
    return make_float2(lo, hi);
}
__device__ __forceinline__ void red4(float* p, float a, float b, float c, float d) {
    asm volatile("red.global.add.v4.f32 [%0], {%1, %2, %3, %4};"
                 :: "l"(p), "f"(a), "f"(b), "f"(c), "f"(d) : "memory");
}

// ---------------- dtype detection for edge_index ----------------
__global__ void detect_kernel(const void* ei) {
    const long long* p = (const long long*)ei;
    bool ok = true;
    for (int i = threadIdx.x; i < 64; i += 32) {
        long long v = p[i];
        if (v < 0 || v >= NN_MAX) ok = false;
    }
    unsigned m = __ballot_sync(0xffffffffu, ok);
    if (threadIdx.x == 0) g_is64 = (m == 0xffffffffu) ? 1 : 0;
}

__global__ void convert_kernel(const void* ei, int E) {
    int i = blockIdx.x * blockDim.x + threadIdx.x;
    if (i >= E) return;
    if (g_is64) {
        const long long* p = (const long long*)ei;
        g_src[i] = (int)p[i];
        g_dst[i] = (int)p[(size_t)E + i];
    } else {
        const int* p = (const int*)ei;
        g_src[i] = p[i];
        g_dst[i] = p[E + i];
    }
}

// accum = features  (re-done every replay; graph replays must be idempotent)
__global__ void init_accum_kernel(const float* __restrict__ feat, int n4) {
    int i = blockIdx.x * blockDim.x + threadIdx.x;
    if (i < n4) ((float4*)g_accum)[i] = ((const float4*)feat)[i];
}

// ---------------- edge MLP + scatter (f32x2 packed) ----------------
// Weight smem layout (conflict-free): for each k, 64 outputs stored as
//   [ pair-quads of jg0..7 for h=0 ][ same for h=1 ]
// i.e. float4 at offset k*64 + h*32 + jg*4 holds outputs j = jg*8 + h*4 + {0..3}.
// A warp (8 jg x 4 ep) reading its float4 covers 128 contiguous bytes -> 1 phase.
__global__ __launch_bounds__(512, 1)
void edge_kernel(const float* __restrict__ feat,
                 const float* __restrict__ ef,
                 const float* __restrict__ W1, const float* __restrict__ b1,
                 const float* __restrict__ W2, const float* __restrict__ b2,
                 int E, int ntiles) {
    extern __shared__ float sm[];
    float* W1s = sm;                        // [192][64] permuted
    float* W2s = W1s + 192 * 64;            // [64][64]  permuted
    float* Xs  = W2s + 64 * 64;             // [TE][XS_STRIDE]
    float* Hs  = Xs + TE * XS_STRIDE;       // [TE][HS_STRIDE]
    int*   srcs = (int*)(Hs + TE * HS_STRIDE);
    int*   dsts = srcs + TE;

    const int tid = threadIdx.x;

    // permuted transpose-load of weights
    for (int idx = tid; idx < 192 * 64; idx += 512) {
        int k = idx >> 6, r = idx & 63;
        int h = r >> 5, jgp = (r >> 2) & 7, u = r & 3;
        int j = jgp * 8 + h * 4 + u;
        W1s[idx] = W1[j * 192 + k];
    }
    for (int idx = tid; idx < 64 * 64; idx += 512) {
        int k = idx >> 6, r = idx & 63;
        int h = r >> 5, jgp = (r >> 2) & 7, u = r & 3;
        int i = jgp * 8 + h * 4 + u;
        W2s[idx] = W2[i * 64 + k];
    }

    const int jg = tid & 7;         // output group: j0 = jg*8 (8 outputs)
    const int ep = tid >> 3;        // edge group (0..63): ebase = ep*2
    const int j0 = jg * 8;
    const int ebase = ep * 2;

    float bb1[8], bb2[8];
#pragma unroll
    for (int u = 0; u < 8; u++) { bb1[u] = b1[j0 + u]; bb2[u] = b2[j0 + u]; }

    for (int t = blockIdx.x; t < ntiles; t += gridDim.x) {
        const int base = t * TE;
        __syncthreads();  // protects smem reuse across iterations

        if (tid < TE) {
            int e = base + tid;
            srcs[tid] = (e < E) ? g_src[e] : 0;
            dsts[tid] = (e < E) ? g_dst[e] : 0;
        }
        __syncthreads();

        // gather X tile: TE edges x 48 float4
        for (int idx = tid; idx < TE * 48; idx += 512) {
            int e = idx / 48, q = idx - e * 48;
            int ge = base + e;
            float4 v;
            if (q < 16)      v = ((const float4*)(feat + (size_t)srcs[e] * D))[q];
            else if (q < 32) v = (ge < E) ? ((const float4*)(ef + (size_t)ge * D))[q - 16]
                                          : make_float4(0.f, 0.f, 0.f, 0.f);
            else             v = ((const float4*)(feat + (size_t)dsts[e] * D))[q - 32];
            *(float4*)(Xs + e * XS_STRIDE + q * 4) = v;
        }
        __syncthreads();

        // ---- stage 1: 192 -> 64, relu ----
        unsigned long long acc[2][4];
#pragma unroll
        for (int c = 0; c < 2; c++)
#pragma unroll
            for (int p = 0; p < 4; p++) acc[c][p] = 0ull;

        const float* xrow = Xs + ebase * XS_STRIDE;
#pragma unroll 8
        for (int k = 0; k < 192; k++) {
            unsigned long long x0 = packf2(xrow[k]);
            unsigned long long x1 = packf2(xrow[XS_STRIDE + k]);
            const float* wp = W1s + (k << 6) + (jg << 2);
            ulonglong2 w0 = *(const ulonglong2*)wp;          // h=0: pairs (0,1),(2,3)
            ulonglong2 w1 = *(const ulonglong2*)(wp + 32);   // h=1: pairs (4,5),(6,7)
            ffma2(acc[0][0], x0, w0.x); ffma2(acc[0][1], x0, w0.y);
            ffma2(acc[0][2], x0, w1.x); ffma2(acc[0][3], x0, w1.y);
            ffma2(acc[1][0], x1, w0.x); ffma2(acc[1][1], x1, w0.y);
            ffma2(acc[1][2], x1, w1.x); ffma2(acc[1][3], x1, w1.y);
        }
#pragma unroll
        for (int c = 0; c < 2; c++) {
            float2 p0 = unpackf2(acc[c][0]);
            float2 p1 = unpackf2(acc[c][1]);
            float2 p2 = unpackf2(acc[c][2]);
            float2 p3 = unpackf2(acc[c][3]);
            float4 ha, hb;
            ha.x = fmaxf(p0.x + bb1[0], 0.f);
            ha.y = fmaxf(p0.y + bb1[1], 0.f);
            ha.z = fmaxf(p1.x + bb1[2], 0.f);
            ha.w = fmaxf(p1.y + bb1[3], 0.f);
            hb.x = fmaxf(p2.x + bb1[4], 0.f);
            hb.y = fmaxf(p2.y + bb1[5], 0.f);
            hb.z = fmaxf(p3.x + bb1[6], 0.f);
            hb.w = fmaxf(p3.y + bb1[7], 0.f);
            *(float4*)(Hs + (ebase + c) * HS_STRIDE + j0) = ha;
            *(float4*)(Hs + (ebase + c) * HS_STRIDE + j0 + 4) = hb;
        }
        __syncthreads();

        // ---- stage 2: 64 -> 64 ----
#pragma unroll
        for (int c = 0; c < 2; c++)
#pragma unroll
            for (int p = 0; p < 4; p++) acc[c][p] = 0ull;

        const float* hrow = Hs + ebase * HS_STRIDE;
#pragma unroll 8
        for (int k = 0; k < 64; k++) {
            unsigned long long x0 = packf2(hrow[k]);
            unsigned long long x1 = packf2(hrow[HS_STRIDE + k]);
            const float* wp = W2s + (k << 6) + (jg << 2);
            ulonglong2 w0 = *(const ulonglong2*)wp;
            ulonglong2 w1 = *(const ulonglong2*)(wp + 32);
            ffma2(acc[0][0], x0, w0.x); ffma2(acc[0][1], x0, w0.y);
            ffma2(acc[0][2], x0, w1.x); ffma2(acc[0][3], x0, w1.y);
            ffma2(acc[1][0], x1, w0.x); ffma2(acc[1][1], x1, w0.y);
            ffma2(acc[1][2], x1, w1.x); ffma2(acc[1][3], x1, w1.y);
        }

        // scatter (sum by src), vectorized reductions
#pragma unroll
        for (int c = 0; c < 2; c++) {
            int e = ebase + c;
            if (base + e < E) {
                float2 p0 = unpackf2(acc[c][0]);
                float2 p1 = unpackf2(acc[c][1]);
                float2 p2 = unpackf2(acc[c][2]);
                float2 p3 = unpackf2(acc[c][3]);
                float* dstp = g_accum + (size_t)srcs[e] * D + j0;
                red4(dstp,     p0.x + bb2[0], p0.y + bb2[1], p1.x + bb2[2], p1.y + bb2[3]);
                red4(dstp + 4, p2.x + bb2[4], p2.y + bb2[5], p3.x + bb2[6], p3.y + bb2[7]);
            }
        }
    }
}

// ---------------- node MLP ----------------
// z = relu([feat | accum] @ W3^T + b3) @ W4^T + b4
__global__ __launch_bounds__(256, 1)
void node_kernel(const float* __restrict__ feat,
                 const float* __restrict__ W3, const float* __restrict__ b3,
                 const float* __restrict__ W4, const float* __restrict__ b4,
                 float* __restrict__ out, int N) {
    extern __shared__ float sm[];
    float* W3s = sm;                        // [128][64]
    float* W4s = W3s + 128 * 64;            // [64][64]
    float* Xs  = W4s + 64 * 64;             // [64][NXS_STRIDE]
    float* Hs  = Xs + 64 * NXS_STRIDE;      // [64][HS_STRIDE]

    const int tid = threadIdx.x;

    for (int idx = tid; idx < 128 * 64; idx += 256) {
        int k = idx >> 6, j = idx & 63;
        W3s[idx] = W3[j * 128 + k];
    }
    for (int idx = tid; idx < 64 * 64; idx += 256) {
        int j = idx >> 6, i = idx & 63;
        W4s[idx] = W4[i * 64 + j];
    }

    const int jg = tid & 15;
    const int ep = tid >> 4;
    const int j0 = jg * 4;
    const int ebase = ep * 4;

    float bb3[4], bb4[4];
#pragma unroll
    for (int u = 0; u < 4; u++) { bb3[u] = b3[j0 + u]; bb4[u] = b4[j0 + u]; }

    const int base = blockIdx.x * 64;
    __syncthreads();

    for (int idx = tid; idx < 64 * 32; idx += 256) {
        int e = idx >> 5, q = idx & 31;
        int node = base + e;
        if (node >= N) node = N - 1;
        float4 v;
        if (q < 16) v = ((const float4*)(feat + (size_t)node * D))[q];
        else        v = ((const float4*)(g_accum + (size_t)node * D))[q - 16];
        *(float4*)(Xs + e * NXS_STRIDE + q * 4) = v;
    }
    __syncthreads();

    float acc[4][4];
#pragma unroll
    for (int c = 0; c < 4; c++)
#pragma unroll
        for (int u = 0; u < 4; u++) acc[c][u] = 0.f;

    const float* xrow = Xs + ebase * NXS_STRIDE;
#pragma unroll 8
    for (int k = 0; k < 128; k++) {
        float x0 = xrow[k];
        float x1 = xrow[NXS_STRIDE + k];
        float x2 = xrow[2 * NXS_STRIDE + k];
        float x3 = xrow[3 * NXS_STRIDE + k];
        float4 w = *(const float4*)(W3s + (k << 6) + j0);
        acc[0][0] += x0 * w.x; acc[0][1] += x0 * w.y; acc[0][2] += x0 * w.z; acc[0][3] += x0 * w.w;
        acc[1][0] += x1 * w.x; acc[1][1] += x1 * w.y; acc[1][2] += x1 * w.z; acc[1][3] += x1 * w.w;
        acc[2][0] += x2 * w.x; acc[2][1] += x2 * w.y; acc[2][2] += x2 * w.z; acc[2][3] += x2 * w.w;
        acc[3][0] += x3 * w.x; acc[3][1] += x3 * w.y; acc[3][2] += x3 * w.z; acc[3][3] += x3 * w.w;
    }
#pragma unroll
    for (int c = 0; c < 4; c++) {
        float4 h;
        h.x = fmaxf(acc[c][0] + bb3[0], 0.f);
        h.y = fmaxf(acc[c][1] + bb3[1], 0.f);
        h.z = fmaxf(acc[c][2] + bb3[2], 0.f);
        h.w = fmaxf(acc[c][3] + bb3[3], 0.f);
        *(float4*)(Hs + (ebase + c) * HS_STRIDE + j0) = h;
    }
    __syncthreads();

#pragma unroll
    for (int c = 0; c < 4; c++)
#pragma unroll
        for (int u = 0; u < 4; u++) acc[c][u] = 0.f;

    const float* hrow = Hs + ebase * HS_STRIDE;
#pragma unroll 8
    for (int k = 0; k < 64; k++) {
        float x0 = hrow[k];
        float x1 = hrow[HS_STRIDE + k];
        float x2 = hrow[2 * HS_STRIDE + k];
        float x3 = hrow[3 * HS_STRIDE + k];
        float4 w = *(const float4*)(W4s + (k << 6) + j0);
        acc[0][0] += x0 * w.x; acc[0][1] += x0 * w.y; acc[0][2] += x0 * w.z; acc[0][3] += x0 * w.w;
        acc[1][0] += x1 * w.x; acc[1][1] += x1 * w.y; acc[1][2] += x1 * w.z; acc[1][3] += x1 * w.w;
        acc[2][0] += x2 * w.x; acc[2][1] += x2 * w.y; acc[2][2] += x2 * w.z; acc[2][3] += x2 * w.w;
        acc[3][0] += x3 * w.x; acc[3][1] += x3 * w.y; acc[3][2] += x3 * w.z; acc[3][3] += x3 * w.w;
    }

#pragma unroll
    for (int c = 0; c < 4; c++) {
        int node = base + ebase + c;
        if (node < N) {
            float4 z;
            z.x = acc[c][0] + bb4[0];
            z.y = acc[c][1] + bb4[1];
            z.z = acc[c][2] + bb4[2];
            z.w = acc[c][3] + bb4[3];
            *(float4*)(out + (size_t)node * D + j0) = z;
        }
    }
}

// ---------------- launch ----------------
static const int EDGE_SMEM = (192 * 64 + 64 * 64 + TE * XS_STRIDE + TE * HS_STRIDE) * 4 + 2 * TE * 4;
static const int NODE_SMEM = (128 * 64 + 64 * 64 + 64 * NXS_STRIDE + 64 * HS_STRIDE) * 4;

extern "C" void kernel_launch(void* const* d_in, const int* in_sizes, int n_in,
                              void* d_out, int out_size) {
    const float* feat = (const float*)d_in[0];
    const void*  ei   = d_in[1];
    const float* ef   = (const float*)d_in[2];
    const float* W1   = (const float*)d_in[3];
    const float* b1   = (const float*)d_in[4];
    const float* W2   = (const float*)d_in[5];
    const float* b2   = (const float*)d_in[6];
    const float* W3   = (const float*)d_in[7];
    const float* b3   = (const float*)d_in[8];
    const float* W4   = (const float*)d_in[9];
    const float* b4   = (const float*)d_in[10];
    float* out = (float*)d_out;

    int N = in_sizes[0] / D;
    int E = in_sizes[2] / D;
    if (N > NN_MAX) N = NN_MAX;
    if (E > NE_MAX) E = NE_MAX;

    cudaFuncSetAttribute(edge_kernel, cudaFuncAttributeMaxDynamicSharedMemorySize, EDGE_SMEM);
    cudaFuncSetAttribute(node_kernel, cudaFuncAttributeMaxDynamicSharedMemorySize, NODE_SMEM);

    detect_kernel<<<1, 32>>>(ei);
    convert_kernel<<<(E + 255) / 256, 256>>>(ei, E);
    init_accum_kernel<<<(N * 16 + 255) / 256, 256>>>(feat, N * 16);

    int etiles = (E + TE - 1) / TE;
    edge_kernel<<<148, 512, EDGE_SMEM>>>(feat, ef, W1, b1, W2, b2, E, etiles);

    int ntiles = (N + 63) / 64;
    node_kernel<<<ntiles, 256, NODE_SMEM>>>(feat, W3, b3, W4, b4, out, N);
}

// round 11
// speedup vs baseline: 1.5514x; 1.3862x over previous
#include <cuda_runtime.h>
#include <cuda_bf16.h>
#include <cstdint>

#define NN_MAX 50000
#define NE_MAX 800000
#define D 64

#define TE 128          // edges per tile, M = 128
#define NTHR 256        // 8 warps x 16 rows

#define HS_STRIDE 68    // node kernel strides (floats)
#define NXS_STRIDE 132

// ---------------- device scratch ----------------
__device__ int   g_is64;
__device__ int   g_src[NE_MAX];
__device__ int   g_dst[NE_MAX];
__device__ float g_accum[(size_t)NN_MAX * D];

// ---------------- edge-kernel smem layout (bytes) ----------------
// bf16 tiles with padded row strides: A/W1 stride 400 B (200 bf16),
// H/W2 stride 144 B (72 bf16). stride mod 128 == 16 -> conflict-free ldmatrix.
#define A_STRIDE   400
#define H_STRIDE   144
#define OFF_SRCS   0
#define OFF_DSTS   512
#define OFF_B1     1024
#define OFF_B2     1280
#define OFF_AH     1536
#define OFF_AL     (OFF_AH + 128 * A_STRIDE)      // +51200
#define OFF_W1H    (OFF_AL + 128 * A_STRIDE)
#define OFF_W1L    (OFF_W1H + 64 * A_STRIDE)      // +25600
#define OFF_HH     (OFF_W1L + 64 * A_STRIDE)
#define OFF_HL     (OFF_HH + 128 * H_STRIDE)      // +18432
#define OFF_W2H    (OFF_HL + 128 * H_STRIDE)
#define OFF_W2L    (OFF_W2H + 64 * H_STRIDE)      // +9216
#define EDGE_SMEM  (OFF_W2L + 64 * H_STRIDE)      // 210432 bytes

__device__ __forceinline__ unsigned smem_u32(const void* p) {
    unsigned a;
    asm("{ .reg .u64 t; cvta.to.shared.u64 t, %1; cvt.u32.u64 %0, t; }" : "=r"(a) : "l"(p));
    return a;
}

// ---------------- baseline-ISA tensor primitives ----------------
__device__ __forceinline__ void ldsm4(unsigned& r0, unsigned& r1, unsigned& r2, unsigned& r3,
                                      unsigned addr) {
    asm volatile("ldmatrix.sync.aligned.m8n8.x4.shared.b16 {%0,%1,%2,%3}, [%4];"
                 : "=r"(r0), "=r"(r1), "=r"(r2), "=r"(r3) : "r"(addr));
}
__device__ __forceinline__ void mma16816(float* c, const unsigned* a, unsigned b0, unsigned b1) {
    asm volatile("mma.sync.aligned.m16n8k16.row.col.f32.bf16.bf16.f32 "
                 "{%0,%1,%2,%3}, {%4,%5,%6,%7}, {%8,%9}, {%0,%1,%2,%3};"
                 : "+f"(c[0]), "+f"(c[1]), "+f"(c[2]), "+f"(c[3])
                 : "r"(a[0]), "r"(a[1]), "r"(a[2]), "r"(a[3]), "r"(b0), "r"(b1));
}
// pack two fp32 -> bf16x2, low 16 bits = lo
__device__ __forceinline__ unsigned pack_bf2(float lo, float hi) {
    unsigned r;
    asm("cvt.rn.bf16x2.f32 %0, %1, %2;" : "=r"(r) : "f"(hi), "f"(lo));
    return r;
}
__device__ __forceinline__ void red2(float* p, float a, float b) {
    asm volatile("red.global.add.v2.f32 [%0], {%1, %2};" :: "l"(p), "f"(a), "f"(b) : "memory");
}

// split float -> (hi bf16 pair, lo bf16 pair) packed words for 2 values
__device__ __forceinline__ void split2(float x, float y, unsigned& hw, unsigned& lw) {
    hw = pack_bf2(x, y);
    float hx = __uint_as_float(hw << 16);
    float hy = __uint_as_float(hw & 0xffff0000u);
    lw = pack_bf2(x - hx, y - hy);
}

// ---------------- dtype detect / index convert / accum init ----------------
__global__ void detect_kernel(const void* ei) {
    const long long* p = (const long long*)ei;
    bool ok = true;
    for (int i = threadIdx.x; i < 64; i += 32) {
        long long v = p[i];
        if (v < 0 || v >= NN_MAX) ok = false;
    }
    unsigned m = __ballot_sync(0xffffffffu, ok);
    if (threadIdx.x == 0) g_is64 = (m == 0xffffffffu) ? 1 : 0;
}

__global__ void convert_kernel(const void* ei, int E) {
    int i = blockIdx.x * blockDim.x + threadIdx.x;
    if (i >= E) return;
    if (g_is64) {
        const long long* p = (const long long*)ei;
        g_src[i] = (int)p[i];
        g_dst[i] = (int)p[(size_t)E + i];
    } else {
        const int* p = (const int*)ei;
        g_src[i] = p[i];
        g_dst[i] = p[E + i];
    }
}

__global__ void init_accum_kernel(const float* __restrict__ feat, int n4) {
    int i = blockIdx.x * blockDim.x + threadIdx.x;
    if (i < n4) ((float4*)g_accum)[i] = ((const float4*)feat)[i];
}

// ---------------- edge kernel: mma.sync bf16 3-term split ----------------
__global__ __launch_bounds__(NTHR, 1)
void edge_kernel(const float* __restrict__ feat,
                 const float* __restrict__ ef,
                 const float* __restrict__ W1, const float* __restrict__ b1,
                 const float* __restrict__ W2, const float* __restrict__ b2,
                 int E, int ntiles) {
    extern __shared__ char smc[];
    const unsigned smem = smem_u32(smc);
    const int tid = threadIdx.x;
    const int wid = tid >> 5;
    const int lid = tid & 31;

    int*   srcs = (int*)(smc + OFF_SRCS);
    int*   dsts = (int*)(smc + OFF_DSTS);
    float* b1s  = (float*)(smc + OFF_B1);
    float* b2s  = (float*)(smc + OFF_B2);

    // --- one-time weight split to bf16 hi/lo, stored [n][k] (col-major B) ---
    for (int idx = tid; idx < 64 * 192; idx += NTHR) {
        int j = idx / 192, k = idx - j * 192;
        float w = W1[idx];
        __nv_bfloat16 bh = __float2bfloat16(w);
        __nv_bfloat16 bl = __float2bfloat16(w - __bfloat162float(bh));
        *(__nv_bfloat16*)(smc + OFF_W1H + j * A_STRIDE + k * 2) = bh;
        *(__nv_bfloat16*)(smc + OFF_W1L + j * A_STRIDE + k * 2) = bl;
    }
    for (int idx = tid; idx < 64 * 64; idx += NTHR) {
        int j = idx >> 6, k = idx & 63;
        float w = W2[idx];
        __nv_bfloat16 bh = __float2bfloat16(w);
        __nv_bfloat16 bl = __float2bfloat16(w - __bfloat162float(bh));
        *(__nv_bfloat16*)(smc + OFF_W2H + j * H_STRIDE + k * 2) = bh;
        *(__nv_bfloat16*)(smc + OFF_W2L + j * H_STRIDE + k * 2) = bl;
    }
    if (tid < 64) { b1s[tid] = b1[tid]; b2s[tid] = b2[tid]; }

    // per-lane ldmatrix offsets
    const int warpR = wid * 16;                                    // A rows for this warp
    const unsigned aoff  = (warpR + (lid & 15)) * A_STRIDE + (lid >> 4) * 16;
    const unsigned hoffA = (warpR + (lid & 15)) * H_STRIDE + (lid >> 4) * 16;
    const int n_r   = (lid & 7) + ((lid >> 4) & 1) * 8;            // B row (output)
    const int n_kad = ((lid >> 3) & 1) * 16;
    const unsigned w1off = n_r * A_STRIDE + n_kad;
    const unsigned w2off = n_r * H_STRIDE + n_kad;
    // C fragment coords
    const int crow = lid >> 2;          // + warpR, and +8 for c2/c3
    const int ccol = (lid & 3) * 2;

    for (int t = blockIdx.x; t < ntiles; t += gridDim.x) {
        const int base = t * TE;
        __syncthreads();  // srcs + smem reuse hazard vs previous tile

        if (tid < TE) {
            int e = base + tid;
            srcs[tid] = (e < E) ? g_src[e] : 0;
            dsts[tid] = (e < E) ? g_dst[e] : 0;
        }
        __syncthreads();

        // --- gather + fp32->bf16 hi/lo split into A tiles (128 x 192) ---
        for (int idx = tid; idx < TE * 48; idx += NTHR) {
            int e = idx / 48, q = idx - e * 48;
            int ge = base + e;
            float4 v;
            if (q < 16)      v = ((const float4*)(feat + (size_t)srcs[e] * D))[q];
            else if (q < 32) v = (ge < E) ? ((const float4*)(ef + (size_t)ge * D))[q - 16]
                                          : make_float4(0.f, 0.f, 0.f, 0.f);
            else             v = ((const float4*)(feat + (size_t)dsts[e] * D))[q - 32];
            unsigned h01, l01, h23, l23;
            split2(v.x, v.y, h01, l01);
            split2(v.z, v.w, h23, l23);
            unsigned bo = e * A_STRIDE + q * 8;
            *(uint2*)(smc + OFF_AH + bo) = make_uint2(h01, h23);
            *(uint2*)(smc + OFF_AL + bo) = make_uint2(l01, l23);
        }
        __syncthreads();

        // --- stage 1: H = relu(X @ W1^T + b1), K=192 (12 ksteps) ---
        float c[8][4];
#pragma unroll
        for (int n = 0; n < 8; n++)
#pragma unroll
            for (int u = 0; u < 4; u++) c[n][u] = 0.f;

#pragma unroll
        for (int ks = 0; ks < 12; ks++) {
            unsigned ah[4], al[4];
            ldsm4(ah[0], ah[1], ah[2], ah[3], smem + OFF_AH + aoff + ks * 32);
            ldsm4(al[0], al[1], al[2], al[3], smem + OFF_AL + aoff + ks * 32);
#pragma unroll
            for (int np = 0; np < 4; np++) {
                unsigned bh0, bh1, bh2, bh3, bl0, bl1, bl2, bl3;
                unsigned wb = np * 16 * A_STRIDE + w1off + ks * 32;
                ldsm4(bh0, bh1, bh2, bh3, smem + OFF_W1H + wb);
                ldsm4(bl0, bl1, bl2, bl3, smem + OFF_W1L + wb);
                mma16816(c[2 * np],     ah, bh0, bh1);
                mma16816(c[2 * np],     al, bh0, bh1);
                mma16816(c[2 * np],     ah, bl0, bl1);
                mma16816(c[2 * np + 1], ah, bh2, bh3);
                mma16816(c[2 * np + 1], al, bh2, bh3);
                mma16816(c[2 * np + 1], ah, bl2, bl3);
            }
        }

        // epilogue 1: relu(+b1), split, store H tiles
        {
            const int r0 = warpR + crow;
            const int r1 = r0 + 8;
#pragma unroll
            for (int n = 0; n < 8; n++) {
                int col = n * 8 + ccol;
                float h0 = fmaxf(c[n][0] + b1s[col],     0.f);
                float h1 = fmaxf(c[n][1] + b1s[col + 1], 0.f);
                float h2 = fmaxf(c[n][2] + b1s[col],     0.f);
                float h3 = fmaxf(c[n][3] + b1s[col + 1], 0.f);
                unsigned hw, lw;
                split2(h0, h1, hw, lw);
                *(unsigned*)(smc + OFF_HH + r0 * H_STRIDE + col * 2) = hw;
                *(unsigned*)(smc + OFF_HL + r0 * H_STRIDE + col * 2) = lw;
                split2(h2, h3, hw, lw);
                *(unsigned*)(smc + OFF_HH + r1 * H_STRIDE + col * 2) = hw;
                *(unsigned*)(smc + OFF_HL + r1 * H_STRIDE + col * 2) = lw;
            }
        }
        __syncthreads();

        // --- stage 2: Z = H @ W2^T + b2, K=64 (4 ksteps) ---
#pragma unroll
        for (int n = 0; n < 8; n++)
#pragma unroll
            for (int u = 0; u < 4; u++) c[n][u] = 0.f;

#pragma unroll
        for (int ks = 0; ks < 4; ks++) {
            unsigned ah[4], al[4];
            ldsm4(ah[0], ah[1], ah[2], ah[3], smem + OFF_HH + hoffA + ks * 32);
            ldsm4(al[0], al[1], al[2], al[3], smem + OFF_HL + hoffA + ks * 32);
#pragma unroll
            for (int np = 0; np < 4; np++) {
                unsigned bh0, bh1, bh2, bh3, bl0, bl1, bl2, bl3;
                unsigned wb = np * 16 * H_STRIDE + w2off + ks * 32;
                ldsm4(bh0, bh1, bh2, bh3, smem + OFF_W2H + wb);
                ldsm4(bl0, bl1, bl2, bl3, smem + OFF_W2L + wb);
                mma16816(c[2 * np],     ah, bh0, bh1);
                mma16816(c[2 * np],     al, bh0, bh1);
                mma16816(c[2 * np],     ah, bl0, bl1);
                mma16816(c[2 * np + 1], ah, bh2, bh3);
                mma16816(c[2 * np + 1], al, bh2, bh3);
                mma16816(c[2 * np + 1], ah, bl2, bl3);
            }
        }

        // scatter: accum[src[row]] += Z row + b2
        {
            const int r0 = warpR + crow;
            const int r1 = r0 + 8;
            const bool v0 = (base + r0 < E);
            const bool v1 = (base + r1 < E);
            float* p0 = g_accum + (size_t)srcs[r0] * D;
            float* p1 = g_accum + (size_t)srcs[r1] * D;
#pragma unroll
            for (int n = 0; n < 8; n++) {
                int col = n * 8 + ccol;
                float bb0 = b2s[col], bb1 = b2s[col + 1];
                if (v0) red2(p0 + col, c[n][0] + bb0, c[n][1] + bb1);
                if (v1) red2(p1 + col, c[n][2] + bb0, c[n][3] + bb1);
            }
        }
    }
}

// ---------------- node MLP (scalar, unchanged) ----------------
__global__ __launch_bounds__(256, 1)
void node_kernel(const float* __restrict__ feat,
                 const float* __restrict__ W3, const float* __restrict__ b3,
                 const float* __restrict__ W4, const float* __restrict__ b4,
                 float* __restrict__ out, int N) {
    extern __shared__ float sm[];
    float* W3s = sm;
    float* W4s = W3s + 128 * 64;
    float* Xs  = W4s + 64 * 64;
    float* Hs  = Xs + 64 * NXS_STRIDE;

    const int tid = threadIdx.x;

    for (int idx = tid; idx < 128 * 64; idx += 256) {
        int k = idx >> 6, j = idx & 63;
        W3s[idx] = W3[j * 128 + k];
    }
    for (int idx = tid; idx < 64 * 64; idx += 256) {
        int j = idx >> 6, i = idx & 63;
        W4s[idx] = W4[i * 64 + j];
    }

    const int jg = tid & 15;
    const int ep = tid >> 4;
    const int j0 = jg * 4;
    const int ebase = ep * 4;

    float bb3[4], bb4[4];
#pragma unroll
    for (int u = 0; u < 4; u++) { bb3[u] = b3[j0 + u]; bb4[u] = b4[j0 + u]; }

    const int base = blockIdx.x * 64;
    __syncthreads();

    for (int idx = tid; idx < 64 * 32; idx += 256) {
        int e = idx >> 5, q = idx & 31;
        int node = base + e;
        if (node >= N) node = N - 1;
        float4 v;
        if (q < 16) v = ((const float4*)(feat + (size_t)node * D))[q];
        else        v = ((const float4*)(g_accum + (size_t)node * D))[q - 16];
        *(float4*)(Xs + e * NXS_STRIDE + q * 4) = v;
    }
    __syncthreads();

    float acc[4][4];
#pragma unroll
    for (int c = 0; c < 4; c++)
#pragma unroll
        for (int u = 0; u < 4; u++) acc[c][u] = 0.f;

    const float* xrow = Xs + ebase * NXS_STRIDE;
#pragma unroll 8
    for (int k = 0; k < 128; k++) {
        float x0 = xrow[k];
        float x1 = xrow[NXS_STRIDE + k];
        float x2 = xrow[2 * NXS_STRIDE + k];
        float x3 = xrow[3 * NXS_STRIDE + k];
        float4 w = *(const float4*)(W3s + (k << 6) + j0);
        acc[0][0] += x0 * w.x; acc[0][1] += x0 * w.y; acc[0][2] += x0 * w.z; acc[0][3] += x0 * w.w;
        acc[1][0] += x1 * w.x; acc[1][1] += x1 * w.y; acc[1][2] += x1 * w.z; acc[1][3] += x1 * w.w;
        acc[2][0] += x2 * w.x; acc[2][1] += x2 * w.y; acc[2][2] += x2 * w.z; acc[2][3] += x2 * w.w;
        acc[3][0] += x3 * w.x; acc[3][1] += x3 * w.y; acc[3][2] += x3 * w.z; acc[3][3] += x3 * w.w;
    }
#pragma unroll
    for (int c = 0; c < 4; c++) {
        float4 h;
        h.x = fmaxf(acc[c][0] + bb3[0], 0.f);
        h.y = fmaxf(acc[c][1] + bb3[1], 0.f);
        h.z = fmaxf(acc[c][2] + bb3[2], 0.f);
        h.w = fmaxf(acc[c][3] + bb3[3], 0.f);
        *(float4*)(Hs + (ebase + c) * HS_STRIDE + j0) = h;
    }
    __syncthreads();

#pragma unroll
    for (int c = 0; c < 4; c++)
#pragma unroll
        for (int u = 0; u < 4; u++) acc[c][u] = 0.f;

    const float* hrow = Hs + ebase * HS_STRIDE;
#pragma unroll 8
    for (int k = 0; k < 64; k++) {
        float x0 = hrow[k];
        float x1 = hrow[HS_STRIDE + k];
        float x2 = hrow[2 * HS_STRIDE + k];
        float x3 = hrow[3 * HS_STRIDE + k];
        float4 w = *(const float4*)(W4s + (k << 6) + j0);
        acc[0][0] += x0 * w.x; acc[0][1] += x0 * w.y; acc[0][2] += x0 * w.z; acc[0][3] += x0 * w.w;
        acc[1][0] += x1 * w.x; acc[1][1] += x1 * w.y; acc[1][2] += x1 * w.z; acc[1][3] += x1 * w.w;
        acc[2][0] += x2 * w.x; acc[2][1] += x2 * w.y; acc[2][2] += x2 * w.z; acc[2][3] += x2 * w.w;
        acc[3][0] += x3 * w.x; acc[3][1] += x3 * w.y; acc[3][2] += x3 * w.z; acc[3][3] += x3 * w.w;
    }

#pragma unroll
    for (int c = 0; c < 4; c++) {
        int node = base + ebase + c;
        if (node < N) {
            float4 z;
            z.x = acc[c][0] + bb4[0];
            z.y = acc[c][1] + bb4[1];
            z.z = acc[c][2] + bb4[2];
            z.w = acc[c][3] + bb4[3];
            *(float4*)(out + (size_t)node * D + j0) = z;
        }
    }
}

// ---------------- launch ----------------
static const int NODE_SMEM = (128 * 64 + 64 * 64 + 64 * NXS_STRIDE + 64 * HS_STRIDE) * 4;

extern "C" void kernel_launch(void* const* d_in, const int* in_sizes, int n_in,
                              void* d_out, int out_size) {
    const float* feat = (const float*)d_in[0];
    const void*  ei   = d_in[1];
    const float* ef   = (const float*)d_in[2];
    const float* W1   = (const float*)d_in[3];
    const float* b1   = (const float*)d_in[4];
    const float* W2   = (const float*)d_in[5];
    const float* b2   = (const float*)d_in[6];
    const float* W3   = (const float*)d_in[7];
    const float* b3   = (const float*)d_in[8];
    const float* W4   = (const float*)d_in[9];
    const float* b4   = (const float*)d_in[10];
    float* out = (float*)d_out;

    int N = in_sizes[0] / D;
    int E = in_sizes[2] / D;
    if (N > NN_MAX) N = NN_MAX;
    if (E > NE_MAX) E = NE_MAX;

    cudaFuncSetAttribute(edge_kernel, cudaFuncAttributeMaxDynamicSharedMemorySize, EDGE_SMEM);
    cudaFuncSetAttribute(node_kernel, cudaFuncAttributeMaxDynamicSharedMemorySize, NODE_SMEM);

    detect_kernel<<<1, 32>>>(ei);
    convert_kernel<<<(E + 255) / 256, 256>>>(ei, E);
    init_accum_kernel<<<(N * 16 + 255) / 256, 256>>>(feat, N * 16);

    int etiles = (E + TE - 1) / TE;
    edge_kernel<<<148, NTHR, EDGE_SMEM>>>(feat, ef, W1, b1, W2, b2, E, etiles);

    int ntiles = (N + 63) / 64;
    node_kernel<<<ntiles, 256, NODE_SMEM>>>(feat, W3, b3, W4, b4, out, N);
}

// round 13
// speedup vs baseline: 2.1858x; 1.4089x over previous
#include <cuda_runtime.h>
#include <cuda_bf16.h>
#include <cstdint>

#define NN_MAX 50000
#define NE_MAX 800000
#define D 64

#define TE 128          // edges per tile, M = 128
#define NTHR 512        // 16 warps: 8 row-groups x 2 col-halves

#define HS_STRIDE 68    // node kernel strides (floats)
#define NXS_STRIDE 132

// ---------------- device scratch ----------------
__device__ int   g_is64;
__device__ int   g_src[NE_MAX];
__device__ int   g_dst[NE_MAX];
__device__ float g_accum[(size_t)NN_MAX * D];

// ---------------- edge-kernel smem layout (bytes) ----------------
// bf16 tiles with padded row strides: A/W1 stride 400 B (200 bf16),
// H/W2 stride 144 B (72 bf16). stride mod 128 == 16 -> conflict-free ldmatrix.
#define A_STRIDE   400
#define H_STRIDE   144
#define OFF_SRCS   0
#define OFF_DSTS   512
#define OFF_B1     1024
#define OFF_B2     1280
#define OFF_AH     1536
#define OFF_AL     (OFF_AH + 128 * A_STRIDE)
#define OFF_W1H    (OFF_AL + 128 * A_STRIDE)
#define OFF_W1L    (OFF_W1H + 64 * A_STRIDE)
#define OFF_HH     (OFF_W1L + 64 * A_STRIDE)
#define OFF_HL     (OFF_HH + 128 * H_STRIDE)
#define OFF_W2H    (OFF_HL + 128 * H_STRIDE)
#define OFF_W2L    (OFF_W2H + 64 * H_STRIDE)
#define EDGE_SMEM  (OFF_W2L + 64 * H_STRIDE)      // 210432 bytes

__device__ __forceinline__ unsigned smem_u32(const void* p) {
    unsigned a;
    asm("{ .reg .u64 t; cvta.to.shared.u64 t, %1; cvt.u32.u64 %0, t; }" : "=r"(a) : "l"(p));
    return a;
}

// ---------------- baseline-ISA tensor primitives ----------------
__device__ __forceinline__ void ldsm4(unsigned& r0, unsigned& r1, unsigned& r2, unsigned& r3,
                                      unsigned addr) {
    asm volatile("ldmatrix.sync.aligned.m8n8.x4.shared.b16 {%0,%1,%2,%3}, [%4];"
                 : "=r"(r0), "=r"(r1), "=r"(r2), "=r"(r3) : "r"(addr));
}
__device__ __forceinline__ void mma16816(float* c, const unsigned* a, unsigned b0, unsigned b1) {
    asm volatile("mma.sync.aligned.m16n8k16.row.col.f32.bf16.bf16.f32 "
                 "{%0,%1,%2,%3}, {%4,%5,%6,%7}, {%8,%9}, {%0,%1,%2,%3};"
                 : "+f"(c[0]), "+f"(c[1]), "+f"(c[2]), "+f"(c[3])
                 : "r"(a[0]), "r"(a[1]), "r"(a[2]), "r"(a[3]), "r"(b0), "r"(b1));
}
// pack two fp32 -> bf16x2, low 16 bits = lo
__device__ __forceinline__ unsigned pack_bf2(float lo, float hi) {
    unsigned r;
    asm("cvt.rn.bf16x2.f32 %0, %1, %2;" : "=r"(r) : "f"(hi), "f"(lo));
    return r;
}
__device__ __forceinline__ void red2(float* p, float a, float b) {
    asm volatile("red.global.add.v2.f32 [%0], {%1, %2};" :: "l"(p), "f"(a), "f"(b) : "memory");
}

// split float -> (hi bf16 pair, lo bf16 pair) packed words for 2 values
__device__ __forceinline__ void split2(float x, float y, unsigned& hw, unsigned& lw) {
    hw = pack_bf2(x, y);
    float hx = __uint_as_float(hw << 16);
    float hy = __uint_as_float(hw & 0xffff0000u);
    lw = pack_bf2(x - hx, y - hy);
}

// ---------------- dtype detect / index convert / accum init ----------------
__global__ void detect_kernel(const void* ei) {
    const long long* p = (const long long*)ei;
    bool ok = true;
    for (int i = threadIdx.x; i < 64; i += 32) {
        long long v = p[i];
        if (v < 0 || v >= NN_MAX) ok = false;
    }
    unsigned m = __ballot_sync(0xffffffffu, ok);
    if (threadIdx.x == 0) g_is64 = (m == 0xffffffffu) ? 1 : 0;
}

__global__ void convert_kernel(const void* ei, int E) {
    int i = blockIdx.x * blockDim.x + threadIdx.x;
    if (i >= E) return;
    if (g_is64) {
        const long long* p = (const long long*)ei;
        g_src[i] = (int)p[i];
        g_dst[i] = (int)p[(size_t)E + i];
    } else {
        const int* p = (const int*)ei;
        g_src[i] = p[i];
        g_dst[i] = p[E + i];
    }
}

__global__ void init_accum_kernel(const float* __restrict__ feat, int n4) {
    int i = blockIdx.x * blockDim.x + threadIdx.x;
    if (i < n4) ((float4*)g_accum)[i] = ((const float4*)feat)[i];
}

// ---------------- edge kernel: mma.sync bf16 3-term split, 16 warps ----------------
__global__ __launch_bounds__(NTHR, 1)
void edge_kernel(const float* __restrict__ feat,
                 const float* __restrict__ ef,
                 const float* __restrict__ W1, const float* __restrict__ b1,
                 const float* __restrict__ W2, const float* __restrict__ b2,
                 int E, int ntiles) {
    extern __shared__ char smc[];
    const unsigned smem = smem_u32(smc);
    const int tid = threadIdx.x;
    const int wid = tid >> 5;
    const int lid = tid & 31;

    int*   srcs = (int*)(smc + OFF_SRCS);
    float* b1s  = (float*)(smc + OFF_B1);
    float* b2s  = (float*)(smc + OFF_B2);

    // --- one-time weight split to bf16 hi/lo, stored [n][k] (col-major B) ---
    for (int idx = tid; idx < 64 * 192; idx += NTHR) {
        int j = idx / 192, k = idx - j * 192;
        float w = W1[idx];
        __nv_bfloat16 bh = __float2bfloat16(w);
        __nv_bfloat16 bl = __float2bfloat16(w - __bfloat162float(bh));
        *(__nv_bfloat16*)(smc + OFF_W1H + j * A_STRIDE + k * 2) = bh;
        *(__nv_bfloat16*)(smc + OFF_W1L + j * A_STRIDE + k * 2) = bl;
    }
    for (int idx = tid; idx < 64 * 64; idx += NTHR) {
        int j = idx >> 6, k = idx & 63;
        float w = W2[idx];
        __nv_bfloat16 bh = __float2bfloat16(w);
        __nv_bfloat16 bl = __float2bfloat16(w - __bfloat162float(bh));
        *(__nv_bfloat16*)(smc + OFF_W2H + j * H_STRIDE + k * 2) = bh;
        *(__nv_bfloat16*)(smc + OFF_W2L + j * H_STRIDE + k * 2) = bl;
    }
    if (tid < 64) { b1s[tid] = b1[tid]; b2s[tid] = b2[tid]; }

    // warp tiling: rowg = wid>>1 selects 16 A rows, colh = wid&1 selects 32-col half
    const int rowg  = wid >> 1;
    const int colh  = wid & 1;
    const int warpR = rowg * 16;
    const int colB  = colh * 32;

    // per-lane ldmatrix offsets
    const unsigned aoff  = (warpR + (lid & 15)) * A_STRIDE + (lid >> 4) * 16;
    const unsigned hoffA = (warpR + (lid & 15)) * H_STRIDE + (lid >> 4) * 16;
    const int n_r   = (lid & 7) + ((lid >> 4) & 1) * 8;            // B row within 16-row group
    const int n_kad = ((lid >> 3) & 1) * 16;
    const unsigned w1off = n_r * A_STRIDE + n_kad;
    const unsigned w2off = n_r * H_STRIDE + n_kad;
    // C fragment coords
    const int crow = lid >> 2;          // + warpR, and +8 for c2/c3
    const int ccol = (lid & 3) * 2;

    for (int t = blockIdx.x; t < ntiles; t += gridDim.x) {
        const int base = t * TE;
        __syncthreads();  // srcs + smem reuse hazard vs previous tile

        if (tid < TE) {
            int e = base + tid;
            srcs[tid]       = (e < E) ? g_src[e] : 0;
            ((int*)(smc + OFF_DSTS))[tid] = (e < E) ? g_dst[e] : 0;
        }
        __syncthreads();

        // --- gather + fp32->bf16 hi/lo split into A tiles (128 x 192) ---
        const int* dsts = (const int*)(smc + OFF_DSTS);
        for (int idx = tid; idx < TE * 48; idx += NTHR) {
            int e = idx / 48, q = idx - e * 48;
            int ge = base + e;
            float4 v;
            if (q < 16)      v = ((const float4*)(feat + (size_t)srcs[e] * D))[q];
            else if (q < 32) v = (ge < E) ? ((const float4*)(ef + (size_t)ge * D))[q - 16]
                                          : make_float4(0.f, 0.f, 0.f, 0.f);
            else             v = ((const float4*)(feat + (size_t)dsts[e] * D))[q - 32];
            unsigned h01, l01, h23, l23;
            split2(v.x, v.y, h01, l01);
            split2(v.z, v.w, h23, l23);
            unsigned bo = e * A_STRIDE + q * 8;
            *(uint2*)(smc + OFF_AH + bo) = make_uint2(h01, h23);
            *(uint2*)(smc + OFF_AL + bo) = make_uint2(l01, l23);
        }
        __syncthreads();

        // --- stage 1: H = relu(X @ W1^T + b1), K=192 (12 ksteps) ---
        float c[4][4];
#pragma unroll
        for (int n = 0; n < 4; n++)
#pragma unroll
            for (int u = 0; u < 4; u++) c[n][u] = 0.f;

#pragma unroll
        for (int ks = 0; ks < 12; ks++) {
            unsigned ah[4], al[4];
            ldsm4(ah[0], ah[1], ah[2], ah[3], smem + OFF_AH + aoff + ks * 32);
            ldsm4(al[0], al[1], al[2], al[3], smem + OFF_AL + aoff + ks * 32);
#pragma unroll
            for (int np = 0; np < 2; np++) {
                unsigned bh0, bh1, bh2, bh3, bl0, bl1, bl2, bl3;
                unsigned wb = (colB + np * 16) * A_STRIDE + w1off + ks * 32;
                ldsm4(bh0, bh1, bh2, bh3, smem + OFF_W1H + wb);
                ldsm4(bl0, bl1, bl2, bl3, smem + OFF_W1L + wb);
                // interleave the two C chains: dependency distance 2
                mma16816(c[2 * np],     ah, bh0, bh1);
                mma16816(c[2 * np + 1], ah, bh2, bh3);
                mma16816(c[2 * np],     al, bh0, bh1);
                mma16816(c[2 * np + 1], al, bh2, bh3);
                mma16816(c[2 * np],     ah, bl0, bl1);
                mma16816(c[2 * np + 1], ah, bl2, bl3);
            }
        }

        // epilogue 1: relu(+b1), split, store H tiles
        {
            const int r0 = warpR + crow;
            const int r1 = r0 + 8;
#pragma unroll
            for (int n = 0; n < 4; n++) {
                int col = colB + n * 8 + ccol;
                float h0 = fmaxf(c[n][0] + b1s[col],     0.f);
                float h1 = fmaxf(c[n][1] + b1s[col + 1], 0.f);
                float h2 = fmaxf(c[n][2] + b1s[col],     0.f);
                float h3 = fmaxf(c[n][3] + b1s[col + 1], 0.f);
                unsigned hw, lw;
                split2(h0, h1, hw, lw);
                *(unsigned*)(smc + OFF_HH + r0 * H_STRIDE + col * 2) = hw;
                *(unsigned*)(smc + OFF_HL + r0 * H_STRIDE + col * 2) = lw;
                split2(h2, h3, hw, lw);
                *(unsigned*)(smc + OFF_HH + r1 * H_STRIDE + col * 2) = hw;
                *(unsigned*)(smc + OFF_HL + r1 * H_STRIDE + col * 2) = lw;
            }
        }
        __syncthreads();

        // --- stage 2: Z = H @ W2^T + b2, K=64 (4 ksteps) ---
#pragma unroll
        for (int n = 0; n < 4; n++)
#pragma unroll
            for (int u = 0; u < 4; u++) c[n][u] = 0.f;

#pragma unroll
        for (int ks = 0; ks < 4; ks++) {
            unsigned ah[4], al[4];
            ldsm4(ah[0], ah[1], ah[2], ah[3], smem + OFF_HH + hoffA + ks * 32);
            ldsm4(al[0], al[1], al[2], al[3], smem + OFF_HL + hoffA + ks * 32);
#pragma unroll
            for (int np = 0; np < 2; np++) {
                unsigned bh0, bh1, bh2, bh3, bl0, bl1, bl2, bl3;
                unsigned wb = (colB + np * 16) * H_STRIDE + w2off + ks * 32;
                ldsm4(bh0, bh1, bh2, bh3, smem + OFF_W2H + wb);
                ldsm4(bl0, bl1, bl2, bl3, smem + OFF_W2L + wb);
                mma16816(c[2 * np],     ah, bh0, bh1);
                mma16816(c[2 * np + 1], ah, bh2, bh3);
                mma16816(c[2 * np],     al, bh0, bh1);
                mma16816(c[2 * np + 1], al, bh2, bh3);
                mma16816(c[2 * np],     ah, bl0, bl1);
                mma16816(c[2 * np + 1], ah, bl2, bl3);
            }
        }

        // scatter: accum[src[row]] += Z row + b2 (each warp: its 32-col half)
        {
            const int r0 = warpR + crow;
            const int r1 = r0 + 8;
            const bool v0 = (base + r0 < E);
            const bool v1 = (base + r1 < E);
            float* p0 = g_accum + (size_t)srcs[r0] * D;
            float* p1 = g_accum + (size_t)srcs[r1] * D;
#pragma unroll
            for (int n = 0; n < 4; n++) {
                int col = colB + n * 8 + ccol;
                float bb0 = b2s[col], bb1 = b2s[col + 1];
                if (v0) red2(p0 + col, c[n][0] + bb0, c[n][1] + bb1);
                if (v1) red2(p1 + col, c[n][2] + bb0, c[n][3] + bb1);
            }
        }
    }
}

// ---------------- node MLP (scalar, unchanged) ----------------
__global__ __launch_bounds__(256, 1)
void node_kernel(const float* __restrict__ feat,
                 const float* __restrict__ W3, const float* __restrict__ b3,
                 const float* __restrict__ W4, const float* __restrict__ b4,
                 float* __restrict__ out, int N) {
    extern __shared__ float sm[];
    float* W3s = sm;
    float* W4s = W3s + 128 * 64;
    float* Xs  = W4s + 64 * 64;
    float* Hs  = Xs + 64 * NXS_STRIDE;

    const int tid = threadIdx.x;

    for (int idx = tid; idx < 128 * 64; idx += 256) {
        int k = idx >> 6, j = idx & 63;
        W3s[idx] = W3[j * 128 + k];
    }
    for (int idx = tid; idx < 64 * 64; idx += 256) {
        int j = idx >> 6, i = idx & 63;
        W4s[idx] = W4[i * 64 + j];
    }

    const int jg = tid & 15;
    const int ep = tid >> 4;
    const int j0 = jg * 4;
    const int ebase = ep * 4;

    float bb3[4], bb4[4];
#pragma unroll
    for (int u = 0; u < 4; u++) { bb3[u] = b3[j0 + u]; bb4[u] = b4[j0 + u]; }

    const int base = blockIdx.x * 64;
    __syncthreads();

    for (int idx = tid; idx < 64 * 32; idx += 256) {
        int e = idx >> 5, q = idx & 31;
        int node = base + e;
        if (node >= N) node = N - 1;
        float4 v;
        if (q < 16) v = ((const float4*)(feat + (size_t)node * D))[q];
        else        v = ((const float4*)(g_accum + (size_t)node * D))[q - 16];
        *(float4*)(Xs + e * NXS_STRIDE + q * 4) = v;
    }
    __syncthreads();

    float acc[4][4];
#pragma unroll
    for (int c = 0; c < 4; c++)
#pragma unroll
        for (int u = 0; u < 4; u++) acc[c][u] = 0.f;

    const float* xrow = Xs + ebase * NXS_STRIDE;
#pragma unroll 8
    for (int k = 0; k < 128; k++) {
        float x0 = xrow[k];
        float x1 = xrow[NXS_STRIDE + k];
        float x2 = xrow[2 * NXS_STRIDE + k];
        float x3 = xrow[3 * NXS_STRIDE + k];
        float4 w = *(const float4*)(W3s + (k << 6) + j0);
        acc[0][0] += x0 * w.x; acc[0][1] += x0 * w.y; acc[0][2] += x0 * w.z; acc[0][3] += x0 * w.w;
        acc[1][0] += x1 * w.x; acc[1][1] += x1 * w.y; acc[1][2] += x1 * w.z; acc[1][3] += x1 * w.w;
        acc[2][0] += x2 * w.x; acc[2][1] += x2 * w.y; acc[2][2] += x2 * w.z; acc[2][3] += x2 * w.w;
        acc[3][0] += x3 * w.x; acc[3][1] += x3 * w.y; acc[3][2] += x3 * w.z; acc[3][3] += x3 * w.w;
    }
#pragma unroll
    for (int c = 0; c < 4; c++) {
        float4 h;
        h.x = fmaxf(acc[c][0] + bb3[0], 0.f);
        h.y = fmaxf(acc[c][1] + bb3[1], 0.f);
        h.z = fmaxf(acc[c][2] + bb3[2], 0.f);
        h.w = fmaxf(acc[c][3] + bb3[3], 0.f);
        *(float4*)(Hs + (ebase + c) * HS_STRIDE + j0) = h;
    }
    __syncthreads();

#pragma unroll
    for (int c = 0; c < 4; c++)
#pragma unroll
        for (int u = 0; u < 4; u++) acc[c][u] = 0.f;

    const float* hrow = Hs + ebase * HS_STRIDE;
#pragma unroll 8
    for (int k = 0; k < 64; k++) {
        float x0 = hrow[k];
        float x1 = hrow[HS_STRIDE + k];
        float x2 = hrow[2 * HS_STRIDE + k];
        float x3 = hrow[3 * HS_STRIDE + k];
        float4 w = *(const float4*)(W4s + (k << 6) + j0);
        acc[0][0] += x0 * w.x; acc[0][1] += x0 * w.y; acc[0][2] += x0 * w.z; acc[0][3] += x0 * w.w;
        acc[1][0] += x1 * w.x; acc[1][1] += x1 * w.y; acc[1][2] += x1 * w.z; acc[1][3] += x1 * w.w;
        acc[2][0] += x2 * w.x; acc[2][1] += x2 * w.y; acc[2][2] += x2 * w.z; acc[2][3] += x2 * w.w;
        acc[3][0] += x3 * w.x; acc[3][1] += x3 * w.y; acc[3][2] += x3 * w.z; acc[3][3] += x3 * w.w;
    }

#pragma unroll
    for (int c = 0; c < 4; c++) {
        int node = base + ebase + c;
        if (node < N) {
            float4 z;
            z.x = acc[c][0] + bb4[0];
            z.y = acc[c][1] + bb4[1];
            z.z = acc[c][2] + bb4[2];
            z.w = acc[c][3] + bb4[3];
            *(float4*)(out + (size_t)node * D + j0) = z;
        }
    }
}

// ---------------- launch ----------------
static const int NODE_SMEM = (128 * 64 + 64 * 64 + 64 * NXS_STRIDE + 64 * HS_STRIDE) * 4;

extern "C" void kernel_launch(void* const* d_in, const int* in_sizes, int n_in,
                              void* d_out, int out_size) {
    const float* feat = (const float*)d_in[0];
    const void*  ei   = d_in[1];
    const float* ef   = (const float*)d_in[2];
    const float* W1   = (const float*)d_in[3];
    const float* b1   = (const float*)d_in[4];
    const float* W2   = (const float*)d_in[5];
    const float* b2   = (const float*)d_in[6];
    const float* W3   = (const float*)d_in[7];
    const float* b3   = (const float*)d_in[8];
    const float* W4   = (const float*)d_in[9];
    const float* b4   = (const float*)d_in[10];
    float* out = (float*)d_out;

    int N = in_sizes[0] / D;
    int E = in_sizes[2] / D;
    if (N > NN_MAX) N = NN_MAX;
    if (E > NE_MAX) E = NE_MAX;

    cudaFuncSetAttribute(edge_kernel, cudaFuncAttributeMaxDynamicSharedMemorySize, EDGE_SMEM);
    cudaFuncSetAttribute(node_kernel, cudaFuncAttributeMaxDynamicSharedMemorySize, NODE_SMEM);

    detect_kernel<<<1, 32>>>(ei);
    convert_kernel<<<(E + 255) / 256, 256>>>(ei, E);
    init_accum_kernel<<<(N * 16 + 255) / 256, 256>>>(feat, N * 16);

    int etiles = (E + TE - 1) / TE;
    edge_kernel<<<148, NTHR, EDGE_SMEM>>>(feat, ef, W1, b1, W2, b2, E, etiles);

    int ntiles = (N + 63) / 64;
    node_kernel<<<ntiles, 256, NODE_SMEM>>>(feat, W3, b3, W4, b4, out, N);
}

// round 15
// speedup vs baseline: 3.1625x; 1.4468x over previous
#include <cuda_runtime.h>
#include <cuda_bf16.h>
#include <cstdint>

#define NN_MAX 50000
#define NE_MAX 800000
#define D 64

#define TE 64           // edges per tile, M = 64 (double-buffered pipeline)
#define NTHR 512        // 16 warps: 4 row-groups x 4 col-quarters

#define HS_STRIDE 68    // node kernel strides (floats)
#define NXS_STRIDE 132

// ---------------- device scratch ----------------
__device__ int   g_is64;
__device__ int   g_src[NE_MAX];
__device__ int   g_dst[NE_MAX];
__device__ float g_accum[(size_t)NN_MAX * D];

// ---------------- edge-kernel smem layout (bytes) ----------------
// strides mod 128 == 16 -> conflict-free ldmatrix
#define A_STRIDE   400   // 192 bf16 + pad
#define H_STRIDE   144   // 64 bf16 + pad
#define OFF_IDX    0                         // 2 bufs x (64 src + 64 dst) ints = 1024
#define OFF_B1     1024
#define OFF_B2     1280
#define OFF_A      1536                      // 2 bufs x (hi 25600 + lo 25600)
#define ABUF(b)    (OFF_A + (b) * 51200)
#define OFF_W1H    (OFF_A + 102400)          // 103936
#define OFF_W1L    (OFF_W1H + 25600)         // 129536
#define OFF_HH     (OFF_W1L + 25600)         // 155136
#define OFF_HL     (OFF_HH + 9216)           // 164352
#define OFF_W2H    (OFF_HL + 9216)           // 173568
#define OFF_W2L    (OFF_W2H + 9216)          // 182784
#define EDGE_SMEM  (OFF_W2L + 9216)          // 192000 bytes

__device__ __forceinline__ unsigned smem_u32(const void* p) {
    unsigned a;
    asm("{ .reg .u64 t; cvta.to.shared.u64 t, %1; cvt.u32.u64 %0, t; }" : "=r"(a) : "l"(p));
    return a;
}

// ---------------- baseline-ISA tensor primitives ----------------
__device__ __forceinline__ void ldsm4(unsigned& r0, unsigned& r1, unsigned& r2, unsigned& r3,
                                      unsigned addr) {
    asm volatile("ldmatrix.sync.aligned.m8n8.x4.shared.b16 {%0,%1,%2,%3}, [%4];"
                 : "=r"(r0), "=r"(r1), "=r"(r2), "=r"(r3) : "r"(addr));
}
__device__ __forceinline__ void mma16816(float* c, const unsigned* a, unsigned b0, unsigned b1) {
    asm volatile("mma.sync.aligned.m16n8k16.row.col.f32.bf16.bf16.f32 "
                 "{%0,%1,%2,%3}, {%4,%5,%6,%7}, {%8,%9}, {%0,%1,%2,%3};"
                 : "+f"(c[0]), "+f"(c[1]), "+f"(c[2]), "+f"(c[3])
                 : "r"(a[0]), "r"(a[1]), "r"(a[2]), "r"(a[3]), "r"(b0), "r"(b1));
}
__device__ __forceinline__ unsigned pack_bf2(float lo, float hi) {
    unsigned r;
    asm("cvt.rn.bf16x2.f32 %0, %1, %2;" : "=r"(r) : "f"(hi), "f"(lo));
    return r;
}
__device__ __forceinline__ void red2(float* p, float a, float b) {
    asm volatile("red.global.add.v2.f32 [%0], {%1, %2};" :: "l"(p), "f"(a), "f"(b) : "memory");
}
__device__ __forceinline__ void split2(float x, float y, unsigned& hw, unsigned& lw) {
    hw = pack_bf2(x, y);
    float hx = __uint_as_float(hw << 16);
    float hy = __uint_as_float(hw & 0xffff0000u);
    lw = pack_bf2(x - hx, y - hy);
}

// ---------------- gather helpers (6 float4 per thread for TE=64) ----------------
__device__ __forceinline__ void gather6(float4* v, const float* __restrict__ feat,
                                        const float* __restrict__ ef,
                                        const int* sb, const int* db,
                                        int base, int E, int tid) {
#pragma unroll
    for (int i = 0; i < 6; i++) {
        int idx = tid + i * NTHR;
        int e = idx / 48, q = idx - e * 48;
        int ge = base + e;
        float4 x;
        if (q < 16)      x = ((const float4*)(feat + (size_t)sb[e] * D))[q];
        else if (q < 32) x = (ge < E) ? ((const float4*)(ef + (size_t)ge * D))[q - 16]
                                      : make_float4(0.f, 0.f, 0.f, 0.f);
        else             x = ((const float4*)(feat + (size_t)db[e] * D))[q - 32];
        v[i] = x;
    }
}
__device__ __forceinline__ void store6(const float4* v, char* smc, int abuf, int tid) {
#pragma unroll
    for (int i = 0; i < 6; i++) {
        int idx = tid + i * NTHR;
        int e = idx / 48, q = idx - e * 48;
        unsigned h01, l01, h23, l23;
        split2(v[i].x, v[i].y, h01, l01);
        split2(v[i].z, v[i].w, h23, l23);
        unsigned bo = e * A_STRIDE + q * 8;
        *(uint2*)(smc + abuf + bo)          = make_uint2(h01, h23);
        *(uint2*)(smc + abuf + 25600 + bo)  = make_uint2(l01, l23);
    }
}

// ---------------- dtype detect / index convert / accum init ----------------
__global__ void detect_kernel(const void* ei) {
    const long long* p = (const long long*)ei;
    bool ok = true;
    for (int i = threadIdx.x; i < 64; i += 32) {
        long long v = p[i];
        if (v < 0 || v >= NN_MAX) ok = false;
    }
    unsigned m = __ballot_sync(0xffffffffu, ok);
    if (threadIdx.x == 0) g_is64 = (m == 0xffffffffu) ? 1 : 0;
}

__global__ void convert_kernel(const void* ei, int E) {
    int i = blockIdx.x * blockDim.x + threadIdx.x;
    if (i >= E) return;
    if (g_is64) {
        const long long* p = (const long long*)ei;
        g_src[i] = (int)p[i];
        g_dst[i] = (int)p[(size_t)E + i];
    } else {
        const int* p = (const int*)ei;
        g_src[i] = p[i];
        g_dst[i] = p[E + i];
    }
}

__global__ void init_accum_kernel(const float* __restrict__ feat, int n4) {
    int i = blockIdx.x * blockDim.x + threadIdx.x;
    if (i < n4) ((float4*)g_accum)[i] = ((const float4*)feat)[i];
}

// ---------------- edge kernel: pipelined mma.sync bf16 3-term split ----------------
__global__ __launch_bounds__(NTHR, 1)
void edge_kernel(const float* __restrict__ feat,
                 const float* __restrict__ ef,
                 const float* __restrict__ W1, const float* __restrict__ b1,
                 const float* __restrict__ W2, const float* __restrict__ b2,
                 int E, int ntiles) {
    extern __shared__ char smc[];
    const unsigned smem = smem_u32(smc);
    const int tid = threadIdx.x;
    const int wid = tid >> 5;
    const int lid = tid & 31;
    const int grid = gridDim.x;

    float* b1s = (float*)(smc + OFF_B1);
    float* b2s = (float*)(smc + OFF_B2);

    // --- one-time weight split to bf16 hi/lo, [n][k] layout ---
    for (int idx = tid; idx < 64 * 192; idx += NTHR) {
        int j = idx / 192, k = idx - j * 192;
        float w = W1[idx];
        __nv_bfloat16 bh = __float2bfloat16(w);
        __nv_bfloat16 bl = __float2bfloat16(w - __bfloat162float(bh));
        *(__nv_bfloat16*)(smc + OFF_W1H + j * A_STRIDE + k * 2) = bh;
        *(__nv_bfloat16*)(smc + OFF_W1L + j * A_STRIDE + k * 2) = bl;
    }
    for (int idx = tid; idx < 64 * 64; idx += NTHR) {
        int j = idx >> 6, k = idx & 63;
        float w = W2[idx];
        __nv_bfloat16 bh = __float2bfloat16(w);
        __nv_bfloat16 bl = __float2bfloat16(w - __bfloat162float(bh));
        *(__nv_bfloat16*)(smc + OFF_W2H + j * H_STRIDE + k * 2) = bh;
        *(__nv_bfloat16*)(smc + OFF_W2L + j * H_STRIDE + k * 2) = bl;
    }
    if (tid < 64) { b1s[tid] = b1[tid]; b2s[tid] = b2[tid]; }

    // warp tiling: 4 row-groups (16 rows) x 4 col-quarters (16 cols)
    const int rowg  = wid >> 2;
    const int colq  = wid & 3;
    const int warpR = rowg * 16;
    const int colB  = colq * 16;

    const unsigned aoff  = (warpR + (lid & 15)) * A_STRIDE + (lid >> 4) * 16;
    const unsigned hoffA = (warpR + (lid & 15)) * H_STRIDE + (lid >> 4) * 16;
    const int n_r   = colB + (lid & 7) + ((lid >> 4) & 1) * 8;
    const int n_kad = ((lid >> 3) & 1) * 16;
    const unsigned w1off = n_r * A_STRIDE + n_kad;
    const unsigned w2off = n_r * H_STRIDE + n_kad;
    const int crow = lid >> 2;
    const int ccol = (lid & 3) * 2;
    const int r0 = warpR + crow;
    const int r1 = r0 + 8;

    const int t0 = blockIdx.x;

    // --- prologue: indices for t0 -> buf0, t0+grid -> buf1 ---
    if (tid < TE) {
        int* ib0 = (int*)(smc + OFF_IDX);
        int* ib1 = (int*)(smc + OFF_IDX + 512);
        int e0 = t0 * TE + tid;
        ib0[tid]      = (t0 < ntiles && e0 < E) ? g_src[e0] : 0;
        ib0[64 + tid] = (t0 < ntiles && e0 < E) ? g_dst[e0] : 0;
        int t1 = t0 + grid;
        int e1 = t1 * TE + tid;
        ib1[tid]      = (t1 < ntiles && e1 < E) ? g_src[e1] : 0;
        ib1[64 + tid] = (t1 < ntiles && e1 < E) ? g_dst[e1] : 0;
    }
    __syncthreads();

    // --- prologue gather: tile t0 -> Abuf0 ---
    if (t0 < ntiles) {
        float4 v[6];
        gather6(v, feat, ef, (const int*)(smc + OFF_IDX),
                (const int*)(smc + OFF_IDX + 256), t0 * TE, E, tid);
        store6(v, smc, ABUF(0), tid);
    }
    __syncthreads();

    int cur = 0;
    for (int t = t0; t < ntiles; t += grid) {
        const int nxt = cur ^ 1;
        const int base = t * TE;
        const int tN  = t + grid;
        const int tNN = t + 2 * grid;

        // scatter indices into registers (stable until internal sync)
        const int* sbc = (const int*)(smc + OFF_IDX + cur * 512);
        const int s0 = sbc[r0];
        const int s1 = sbc[r1];

        // index loads for tile t+2 (held in regs)
        int siN = 0, diN = 0;
        if (tid < TE && tNN < ntiles) {
            int e2 = tNN * TE + tid;
            siN = (e2 < E) ? g_src[e2] : 0;
            diN = (e2 < E) ? g_dst[e2] : 0;
        }

        // issue gather LDGs for tile t+1 (fly under stage-1 MMAs)
        float4 v[6];
        const bool haveN = (tN < ntiles);
        if (haveN)
            gather6(v, feat, ef, (const int*)(smc + OFF_IDX + nxt * 512),
                    (const int*)(smc + OFF_IDX + nxt * 512 + 256), tN * TE, E, tid);

        // --- stage 1: H = relu(X @ W1^T + b1), K=192 ---
        float c[2][4];
#pragma unroll
        for (int n = 0; n < 2; n++)
#pragma unroll
            for (int u = 0; u < 4; u++) c[n][u] = 0.f;

        const unsigned aH = smem + ABUF(cur);
        const unsigned aL = aH + 25600;
#pragma unroll
        for (int ks = 0; ks < 12; ks++) {
            unsigned ah[4], al[4];
            unsigned bh0, bh1, bh2, bh3, bl0, bl1, bl2, bl3;
            ldsm4(ah[0], ah[1], ah[2], ah[3], aH + aoff + ks * 32);
            ldsm4(al[0], al[1], al[2], al[3], aL + aoff + ks * 32);
            ldsm4(bh0, bh1, bh2, bh3, smem + OFF_W1H + w1off + ks * 32);
            ldsm4(bl0, bl1, bl2, bl3, smem + OFF_W1L + w1off + ks * 32);
            mma16816(c[0], ah, bh0, bh1);
            mma16816(c[1], ah, bh2, bh3);
            mma16816(c[0], al, bh0, bh1);
            mma16816(c[1], al, bh2, bh3);
            mma16816(c[0], ah, bl0, bl1);
            mma16816(c[1], ah, bl2, bl3);
        }

        // epilogue 1: relu(+b1), split, store H
#pragma unroll
        for (int n = 0; n < 2; n++) {
            int col = colB + n * 8 + ccol;
            float h0 = fmaxf(c[n][0] + b1s[col],     0.f);
            float h1 = fmaxf(c[n][1] + b1s[col + 1], 0.f);
            float h2 = fmaxf(c[n][2] + b1s[col],     0.f);
            float h3 = fmaxf(c[n][3] + b1s[col + 1], 0.f);
            unsigned hw, lw;
            split2(h0, h1, hw, lw);
            *(unsigned*)(smc + OFF_HH + r0 * H_STRIDE + col * 2) = hw;
            *(unsigned*)(smc + OFF_HL + r0 * H_STRIDE + col * 2) = lw;
            split2(h2, h3, hw, lw);
            *(unsigned*)(smc + OFF_HH + r1 * H_STRIDE + col * 2) = hw;
            *(unsigned*)(smc + OFF_HL + r1 * H_STRIDE + col * 2) = lw;
        }
        __syncthreads();

        // --- stage 2: Z = H @ W2^T + b2, K=64 ---
#pragma unroll
        for (int n = 0; n < 2; n++)
#pragma unroll
            for (int u = 0; u < 4; u++) c[n][u] = 0.f;

#pragma unroll
        for (int ks = 0; ks < 4; ks++) {
            unsigned ah[4], al[4];
            unsigned bh0, bh1, bh2, bh3, bl0, bl1, bl2, bl3;
            ldsm4(ah[0], ah[1], ah[2], ah[3], smem + OFF_HH + hoffA + ks * 32);
            ldsm4(al[0], al[1], al[2], al[3], smem + OFF_HL + hoffA + ks * 32);
            ldsm4(bh0, bh1, bh2, bh3, smem + OFF_W2H + w2off + ks * 32);
            ldsm4(bl0, bl1, bl2, bl3, smem + OFF_W2L + w2off + ks * 32);
            mma16816(c[0], ah, bh0, bh1);
            mma16816(c[1], ah, bh2, bh3);
            mma16816(c[0], al, bh0, bh1);
            mma16816(c[1], al, bh2, bh3);
            mma16816(c[0], ah, bl0, bl1);
            mma16816(c[1], ah, bl2, bl3);
        }

        // scatter: accum[src[row]] += Z row + b2 (16-col quarter per warp)
        {
            const bool ok0 = (base + r0 < E);
            const bool ok1 = (base + r1 < E);
            float* p0 = g_accum + (size_t)s0 * D;
            float* p1 = g_accum + (size_t)s1 * D;
#pragma unroll
            for (int n = 0; n < 2; n++) {
                int col = colB + n * 8 + ccol;
                float bb0 = b2s[col], bb1 = b2s[col + 1];
                if (ok0) red2(p0 + col, c[0 + n][0] * 0.f + c[n][0] + bb0 - c[n][0] + c[n][0], c[n][1] + bb1);
                if (ok1) red2(p1 + col, c[n][2] + bb0, c[n][3] + bb1);
            }
        }

        // store t+2 indices into idxbuf[cur] (safe: all top-section reads done)
        if (tid < TE) {
            int* ib = (int*)(smc + OFF_IDX + cur * 512);
            ib[tid]      = siN;
            ib[64 + tid] = diN;
        }

        // convert + store gathered tile t+1 into Abuf[nxt]
        if (haveN) store6(v, smc, ABUF(nxt), tid);
        __syncthreads();
        cur = nxt;
    }
}

// ---------------- node MLP (scalar, unchanged) ----------------
__global__ __launch_bounds__(256, 1)
void node_kernel(const float* __restrict__ feat,
                 const float* __restrict__ W3, const float* __restrict__ b3,
                 const float* __restrict__ W4, const float* __restrict__ b4,
                 float* __restrict__ out, int N) {
    extern __shared__ float sm[];
    float* W3s = sm;
    float* W4s = W3s + 128 * 64;
    float* Xs  = W4s + 64 * 64;
    float* Hs  = Xs + 64 * NXS_STRIDE;

    const int tid = threadIdx.x;

    for (int idx = tid; idx < 128 * 64; idx += 256) {
        int k = idx >> 6, j = idx & 63;
        W3s[idx] = W3[j * 128 + k];
    }
    for (int idx = tid; idx < 64 * 64; idx += 256) {
        int j = idx >> 6, i = idx & 63;
        W4s[idx] = W4[i * 64 + j];
    }

    const int jg = tid & 15;
    const int ep = tid >> 4;
    const int j0 = jg * 4;
    const int ebase = ep * 4;

    float bb3[4], bb4[4];
#pragma unroll
    for (int u = 0; u < 4; u++) { bb3[u] = b3[j0 + u]; bb4[u] = b4[j0 + u]; }

    const int base = blockIdx.x * 64;
    __syncthreads();

    for (int idx = tid; idx < 64 * 32; idx += 256) {
        int e = idx >> 5, q = idx & 31;
        int node = base + e;
        if (node >= N) node = N - 1;
        float4 v;
        if (q < 16) v = ((const float4*)(feat + (size_t)node * D))[q];
        else        v = ((const float4*)(g_accum + (size_t)node * D))[q - 16];
        *(float4*)(Xs + e * NXS_STRIDE + q * 4) = v;
    }
    __syncthreads();

    float acc[4][4];
#pragma unroll
    for (int c = 0; c < 4; c++)
#pragma unroll
        for (int u = 0; u < 4; u++) acc[c][u] = 0.f;

    const float* xrow = Xs + ebase * NXS_STRIDE;
#pragma unroll 8
    for (int k = 0; k < 128; k++) {
        float x0 = xrow[k];
        float x1 = xrow[NXS_STRIDE + k];
        float x2 = xrow[2 * NXS_STRIDE + k];
        float x3 = xrow[3 * NXS_STRIDE + k];
        float4 w = *(const float4*)(W3s + (k << 6) + j0);
        acc[0][0] += x0 * w.x; acc[0][1] += x0 * w.y; acc[0][2] += x0 * w.z; acc[0][3] += x0 * w.w;
        acc[1][0] += x1 * w.x; acc[1][1] += x1 * w.y; acc[1][2] += x1 * w.z; acc[1][3] += x1 * w.w;
        acc[2][0] += x2 * w.x; acc[2][1] += x2 * w.y; acc[2][2] += x2 * w.z; acc[2][3] += x2 * w.w;
        acc[3][0] += x3 * w.x; acc[3][1] += x3 * w.y; acc[3][2] += x3 * w.z; acc[3][3] += x3 * w.w;
    }
#pragma unroll
    for (int c = 0; c < 4; c++) {
        float4 h;
        h.x = fmaxf(acc[c][0] + bb3[0], 0.f);
        h.y = fmaxf(acc[c][1] + bb3[1], 0.f);
        h.z = fmaxf(acc[c][2] + bb3[2], 0.f);
        h.w = fmaxf(acc[c][3] + bb3[3], 0.f);
        *(float4*)(Hs + (ebase + c) * HS_STRIDE + j0) = h;
    }
    __syncthreads();

#pragma unroll
    for (int c = 0; c < 4; c++)
#pragma unroll
        for (int u = 0; u < 4; u++) acc[c][u] = 0.f;

    const float* hrow = Hs + ebase * HS_STRIDE;
#pragma unroll 8
    for (int k = 0; k < 64; k++) {
        float x0 = hrow[k];
        float x1 = hrow[HS_STRIDE + k];
        float x2 = hrow[2 * HS_STRIDE + k];
        float x3 = hrow[3 * HS_STRIDE + k];
        float4 w = *(const float4*)(W4s + (k << 6) + j0);
        acc[0][0] += x0 * w.x; acc[0][1] += x0 * w.y; acc[0][2] += x0 * w.z; acc[0][3] += x0 * w.w;
        acc[1][0] += x1 * w.x; acc[1][1] += x1 * w.y; acc[1][2] += x1 * w.z; acc[1][3] += x1 * w.w;
        acc[2][0] += x2 * w.x; acc[2][1] += x2 * w.y; acc[2][2] += x2 * w.z; acc[2][3] += x2 * w.w;
        acc[3][0] += x3 * w.x; acc[3][1] += x3 * w.y; acc[3][2] += x3 * w.z; acc[3][3] += x3 * w.w;
    }

#pragma unroll
    for (int c = 0; c < 4; c++) {
        int node = base + ebase + c;
        if (node < N) {
            float4 z;
            z.x = acc[c][0] + bb4[0];
            z.y = acc[c][1] + bb4[1];
            z.z = acc[c][2] + bb4[2];
            z.w = acc[c][3] + bb4[3];
            *(float4*)(out + (size_t)node * D + j0) = z;
        }
    }
}

// ---------------- launch ----------------
static const int NODE_SMEM = (128 * 64 + 64 * 64 + 64 * NXS_STRIDE + 64 * HS_STRIDE) * 4;

extern "C" void kernel_launch(void* const* d_in, const int* in_sizes, int n_in,
                              void* d_out, int out_size) {
    const float* feat = (const float*)d_in[0];
    const void*  ei   = d_in[1];
    const float* ef   = (const float*)d_in[2];
    const float* W1   = (const float*)d_in[3];
    const float* b1   = (const float*)d_in[4];
    const float* W2   = (const float*)d_in[5];
    const float* b2   = (const float*)d_in[6];
    const float* W3   = (const float*)d_in[7];
    const float* b3   = (const float*)d_in[8];
    const float* W4   = (const float*)d_in[9];
    const float* b4   = (const float*)d_in[10];
    float* out = (float*)d_out;

    int N = in_sizes[0] / D;
    int E = in_sizes[2] / D;
    if (N > NN_MAX) N = NN_MAX;
    if (E > NE_MAX) E = NE_MAX;

    cudaFuncSetAttribute(edge_kernel, cudaFuncAttributeMaxDynamicSharedMemorySize, EDGE_SMEM);
    cudaFuncSetAttribute(node_kernel, cudaFuncAttributeMaxDynamicSharedMemorySize, NODE_SMEM);

    detect_kernel<<<1, 32>>>(ei);
    convert_kernel<<<(E + 255) / 256, 256>>>(ei, E);
    init_accum_kernel<<<(N * 16 + 255) / 256, 256>>>(feat, N * 16);

    int etiles = (E + TE - 1) / TE;
    edge_kernel<<<148, NTHR, EDGE_SMEM>>>(feat, ef, W1, b1, W2, b2, E, etiles);

    int ntiles = (N + 63) / 64;
    node_kernel<<<ntiles, 256, NODE_SMEM>>>(feat, W3, b3, W4, b4, out, N);
}